// round 4
// baseline (speedup 1.0000x reference)
#include <cuda_runtime.h>
#include <stdint.h>
#include <math.h>

#define BATCH  4
#define NHEADS 16
#define HEAD   64
#define SEQ    2048
#define EMBED  1024
#define QKVN   3072
#define NTOK   (BATCH * SEQ)   // 8192

// ---------------- scratch (device globals: allocation-free) ----------------
__device__ float g_q[BATCH * NHEADS * SEQ * HEAD];   // [B,H,S,D], tf32-rounded, Q pre-scaled
__device__ float g_k[BATCH * NHEADS * SEQ * HEAD];
__device__ float g_v[BATCH * NHEADS * SEQ * HEAD];
__device__ float g_attn[BATCH * SEQ * EMBED];        // [B,S,H*D], tf32-rounded
__device__ float g_xr[NTOK * EMBED];                 // X, tf32-rounded
__device__ float g_wqkv[EMBED * QKVN];               // packed [k][n], tf32-rounded
__device__ float g_wot[EMBED * EMBED];               // Wo^T [f][e], tf32-rounded

// ---------------- helpers ----------------
__device__ __forceinline__ float rnd32(float f) {
    uint32_t r;
    asm("cvt.rna.tf32.f32 %0, %1;" : "=r"(r) : "f"(f));
    return __uint_as_float(r);
}

__device__ __forceinline__ void mma8(float* c,
                                     uint32_t a0, uint32_t a1, uint32_t a2, uint32_t a3,
                                     uint32_t b0, uint32_t b1) {
    asm volatile(
        "mma.sync.aligned.m16n8k8.row.col.f32.tf32.tf32.f32 "
        "{%0,%1,%2,%3}, {%4,%5,%6,%7}, {%8,%9}, {%0,%1,%2,%3};"
        : "+f"(c[0]), "+f"(c[1]), "+f"(c[2]), "+f"(c[3])
        : "r"(a0), "r"(a1), "r"(a2), "r"(a3), "r"(b0), "r"(b1));
}

__device__ __forceinline__ void cp16(void* smem, const void* gmem) {
    uint32_t sa = (uint32_t)__cvta_generic_to_shared(smem);
    asm volatile("cp.async.cg.shared.global [%0], [%1], 16;" :: "r"(sa), "l"(gmem));
}
#define CP_COMMIT() asm volatile("cp.async.commit_group;")
#define CP_WAIT0()  asm volatile("cp.async.wait_group 0;")

// ============================================================================
// Prep kernels: round/pack operands once so inner loops need no cvt.
// ============================================================================
__global__ __launch_bounds__(256) void round_x_kernel(const float* __restrict__ x) {
    int i = (blockIdx.x * 256 + threadIdx.x) * 4;
    float4 v = *(const float4*)(x + i);
    v.x = rnd32(v.x); v.y = rnd32(v.y); v.z = rnd32(v.z); v.w = rnd32(v.w);
    *(float4*)(g_xr + i) = v;
}

__global__ __launch_bounds__(256) void pack_w_kernel(
    const float* __restrict__ Wq, const float* __restrict__ Wk, const float* __restrict__ Wv) {
    int i = blockIdx.x * 256 + threadIdx.x;      // over EMBED*QKVN
    int n = i % QKVN;
    int k = i / QKVN;
    int mat = n >> 10;
    int hn  = n & 1023;
    int h = hn >> 6, d = hn & 63;
    const float* w = (mat == 0) ? Wq : ((mat == 1) ? Wk : Wv);
    g_wqkv[i] = rnd32(w[((size_t)h * EMBED + k) * HEAD + d]);
}

__global__ __launch_bounds__(256) void trans_wo_kernel(const float* __restrict__ Wo) {
    __shared__ float t[32][33];
    const int e0 = blockIdx.x * 32;
    const int f0 = blockIdx.y * 32;
    const int tx = threadIdx.x & 31;
    const int ty = threadIdx.x >> 5;   // 0..7
    #pragma unroll
    for (int j = 0; j < 4; j++)
        t[ty + j * 8][tx] = Wo[(size_t)(e0 + ty + j * 8) * EMBED + f0 + tx];
    __syncthreads();
    #pragma unroll
    for (int j = 0; j < 4; j++)
        g_wot[(size_t)(f0 + ty + j * 8) * EMBED + e0 + tx] = rnd32(t[tx][ty + j * 8]);
}

// ============================================================================
// Kernel 1: QKV GEMM.  g_xr[8192,1024] @ g_wqkv[1024,3072] -> scatter to
// g_q/g_k/g_v [B,H,S,D] (tf32-rounded, Q pre-scaled).  128x128 tiles, 2-stage.
// ============================================================================
__global__ __launch_bounds__(256) void qkv_kernel()
{
    __shared__ float As[2][128][20];
    __shared__ float Bs[2][16][136];

    const int n0 = blockIdx.x * 128;
    const int m0 = blockIdx.y * 128;

    const int tid  = threadIdx.x;
    const int lane = tid & 31;
    const int warp = tid >> 5;
    const int g    = lane >> 2;
    const int t4   = lane & 3;
    const int wm   = warp & 3;
    const int wn   = warp >> 2;

    // staging descriptors
    int arA[2], acA[2], bkB[2], bcB[2];
    const float* agp[2];
    const float* bgp[2];
    #pragma unroll
    for (int j = 0; j < 2; j++) {
        int chunk = tid + j * 256;
        arA[j] = chunk >> 2; acA[j] = (chunk & 3) * 4;
        agp[j] = g_xr + (size_t)(m0 + arA[j]) * EMBED + acA[j];
        bkB[j] = chunk >> 5; bcB[j] = (chunk & 31) * 4;
        bgp[j] = g_wqkv + (size_t)bkB[j] * QKVN + n0 + bcB[j];
    }

    float c[2][8][4];
    #pragma unroll
    for (int mi = 0; mi < 2; mi++)
        #pragma unroll
        for (int ni = 0; ni < 8; ni++)
            #pragma unroll
            for (int e = 0; e < 4; e++) c[mi][ni][e] = 0.0f;

    #pragma unroll
    for (int j = 0; j < 2; j++) {
        cp16(&As[0][arA[j]][acA[j]], agp[j]);
        cp16(&Bs[0][bkB[j]][bcB[j]], bgp[j]);
    }
    CP_COMMIT();
    CP_WAIT0();
    __syncthreads();

    const int NK = EMBED / 16;
    #pragma unroll 2
    for (int it = 0; it < NK; it++) {
        const int buf = it & 1;
        if (it + 1 < NK) {
            const int kc = (it + 1) * 16;
            #pragma unroll
            for (int j = 0; j < 2; j++) {
                cp16(&As[buf ^ 1][arA[j]][acA[j]], agp[j] + kc);
                cp16(&Bs[buf ^ 1][bkB[j]][bcB[j]], bgp[j] + (size_t)kc * QKVN);
            }
            CP_COMMIT();
        }

        #pragma unroll
        for (int ks = 0; ks < 2; ks++) {
            const int kb = ks * 8;
            uint32_t a[2][4];
            #pragma unroll
            for (int mi = 0; mi < 2; mi++) {
                int r = wm * 32 + mi * 16;
                a[mi][0] = __float_as_uint(As[buf][r + g    ][kb + t4]);
                a[mi][1] = __float_as_uint(As[buf][r + g + 8][kb + t4]);
                a[mi][2] = __float_as_uint(As[buf][r + g    ][kb + t4 + 4]);
                a[mi][3] = __float_as_uint(As[buf][r + g + 8][kb + t4 + 4]);
            }
            #pragma unroll
            for (int ni = 0; ni < 8; ni++) {
                uint32_t b0 = __float_as_uint(Bs[buf][kb + t4    ][wn * 64 + ni * 8 + g]);
                uint32_t b1 = __float_as_uint(Bs[buf][kb + t4 + 4][wn * 64 + ni * 8 + g]);
                #pragma unroll
                for (int mi = 0; mi < 2; mi++)
                    mma8(c[mi][ni], a[mi][0], a[mi][1], a[mi][2], a[mi][3], b0, b1);
            }
        }

        CP_WAIT0();
        __syncthreads();
    }

    // epilogue: scatter to [B,H,S,D], round to tf32, pre-scale Q
    const int mat = n0 >> 10;
    const int b   = m0 >> 11;
    const int s0l = m0 & 2047;
    const int h   = ((n0 & 1023) >> 6) + wn;
    float* dstm = (mat == 0) ? g_q : ((mat == 1) ? g_k : g_v);
    float* dst  = dstm + ((size_t)(b * NHEADS + h) * SEQ) * HEAD;
    const float scale = (mat == 0) ? 0.125f : 1.0f;

    #pragma unroll
    for (int mi = 0; mi < 2; mi++) {
        int s0r = s0l + wm * 32 + mi * 16 + g;
        #pragma unroll
        for (int ni = 0; ni < 8; ni++) {
            int d = ni * 8 + t4 * 2;
            dst[(size_t)(s0r    ) * HEAD + d    ] = rnd32(c[mi][ni][0] * scale);
            dst[(size_t)(s0r    ) * HEAD + d + 1] = rnd32(c[mi][ni][1] * scale);
            dst[(size_t)(s0r + 8) * HEAD + d    ] = rnd32(c[mi][ni][2] * scale);
            dst[(size_t)(s0r + 8) * HEAD + d + 1] = rnd32(c[mi][ni][3] * scale);
        }
    }
}

// ============================================================================
// Kernel 2: causal flash attention.  All operands pre-rounded -> no inner cvt.
// BM=128 (8 warps x 16 rows), BN=32, D=64.  Register-staged K/V prefetch.
// ============================================================================
__global__ __launch_bounds__(256, 1) void attn_kernel()
{
    __shared__ float Ks[32][68];    // stride==4 mod 32
    __shared__ float Vs[32][72];    // stride==8 mod 32
    __shared__ float Ps[128][36];   // stride==4 mod 32

    const int bh = blockIdx.y;
    const int b  = bh >> 4;
    const int h  = bh & 15;
    const int qt = blockIdx.x;
    const int q0 = qt * 128;

    const int tid  = threadIdx.x;
    const int lane = tid & 31;
    const int warp = tid >> 5;
    const int g    = lane >> 2;
    const int t4   = lane & 3;

    const float* qp = g_q + ((size_t)bh * SEQ + q0) * HEAD;
    const float* kp = g_k + (size_t)bh * SEQ * HEAD;
    const float* vp = g_v + (size_t)bh * SEQ * HEAD;

    // ---- stage Q through Ps, build A-frags (raw bits; already rounded) ----
    uint32_t qa[8][4];
    #pragma unroll
    for (int round = 0; round < 2; round++) {
        const int c0 = round * 32;
        #pragma unroll
        for (int i = tid; i < 128 * 32; i += 256) {
            int r = i >> 5, cc = i & 31;
            Ps[r][cc] = qp[(size_t)r * HEAD + c0 + cc];
        }
        __syncthreads();
        #pragma unroll
        for (int kf = 0; kf < 4; kf++) {
            int kfi = round * 4 + kf;
            int rr = warp * 16;
            qa[kfi][0] = __float_as_uint(Ps[rr + g    ][kf * 8 + t4]);
            qa[kfi][1] = __float_as_uint(Ps[rr + g + 8][kf * 8 + t4]);
            qa[kfi][2] = __float_as_uint(Ps[rr + g    ][kf * 8 + t4 + 4]);
            qa[kfi][3] = __float_as_uint(Ps[rr + g + 8][kf * 8 + t4 + 4]);
        }
        __syncthreads();
    }

    float o[8][4];
    #pragma unroll
    for (int dn = 0; dn < 8; dn++)
        #pragma unroll
        for (int e = 0; e < 4; e++) o[dn][e] = 0.0f;

    float m0 = -1e30f, m1 = -1e30f, l0 = 0.0f, l1 = 0.0f;

    const int nkt   = (qt + 1) * 4;
    const int row0b = q0 + warp * 16;
    const int qmaxw = row0b + 15;

    float rk[8], rv[8];
    #pragma unroll
    for (int j = 0; j < 8; j++) {
        int i = tid + j * 256;
        int r = i >> 6, d = i & 63;
        rk[j] = kp[(size_t)r * HEAD + d];
        rv[j] = vp[(size_t)r * HEAD + d];
    }
    #pragma unroll
    for (int j = 0; j < 8; j++) {
        int i = tid + j * 256;
        int r = i >> 6, d = i & 63;
        Ks[r][d] = rk[j];
        Vs[r][d] = rv[j];
    }
    __syncthreads();

    for (int kt = 0; kt < nkt; kt++) {
        const int k0 = kt * 32;

        if (kt + 1 < nkt) {
            const size_t nb = (size_t)(k0 + 32) * HEAD;
            #pragma unroll
            for (int j = 0; j < 8; j++) {
                int i = tid + j * 256;
                int r = i >> 6, d = i & 63;
                rk[j] = kp[nb + (size_t)r * HEAD + d];
                rv[j] = vp[nb + (size_t)r * HEAD + d];
            }
        }

        if (k0 <= qmaxw) {
            // ---- S = Q K^T ----
            float s[4][4];
            #pragma unroll
            for (int nf = 0; nf < 4; nf++)
                #pragma unroll
                for (int e = 0; e < 4; e++) s[nf][e] = 0.0f;

            #pragma unroll
            for (int kf = 0; kf < 8; kf++) {
                #pragma unroll
                for (int nf = 0; nf < 4; nf++) {
                    uint32_t b0 = __float_as_uint(Ks[nf * 8 + g][kf * 8 + t4]);
                    uint32_t b1 = __float_as_uint(Ks[nf * 8 + g][kf * 8 + t4 + 4]);
                    mma8(s[nf], qa[kf][0], qa[kf][1], qa[kf][2], qa[kf][3], b0, b1);
                }
            }

            // ---- causal mask ----
            const int r0 = row0b + g;
            const int r1 = r0 + 8;
            #pragma unroll
            for (int nf = 0; nf < 4; nf++) {
                int col0 = k0 + nf * 8 + t4 * 2;
                if (col0     > r0) s[nf][0] = -1e30f;
                if (col0 + 1 > r0) s[nf][1] = -1e30f;
                if (col0     > r1) s[nf][2] = -1e30f;
                if (col0 + 1 > r1) s[nf][3] = -1e30f;
            }

            // ---- online softmax ----
            float rm0 = -1e30f, rm1 = -1e30f;
            #pragma unroll
            for (int nf = 0; nf < 4; nf++) {
                rm0 = fmaxf(rm0, fmaxf(s[nf][0], s[nf][1]));
                rm1 = fmaxf(rm1, fmaxf(s[nf][2], s[nf][3]));
            }
            rm0 = fmaxf(rm0, __shfl_xor_sync(0xffffffffu, rm0, 1));
            rm0 = fmaxf(rm0, __shfl_xor_sync(0xffffffffu, rm0, 2));
            rm1 = fmaxf(rm1, __shfl_xor_sync(0xffffffffu, rm1, 1));
            rm1 = fmaxf(rm1, __shfl_xor_sync(0xffffffffu, rm1, 2));

            float nm0 = fmaxf(m0, rm0), nm1 = fmaxf(m1, rm1);
            float sc0 = __expf(m0 - nm0), sc1 = __expf(m1 - nm1);

            float sum0 = 0.0f, sum1 = 0.0f;
            const int rr = warp * 16;
            #pragma unroll
            for (int nf = 0; nf < 4; nf++) {
                float p0 = rnd32(__expf(s[nf][0] - nm0));
                float p1 = rnd32(__expf(s[nf][1] - nm0));
                float p2 = rnd32(__expf(s[nf][2] - nm1));
                float p3 = rnd32(__expf(s[nf][3] - nm1));
                Ps[rr + g    ][nf * 8 + t4 * 2    ] = p0;
                Ps[rr + g    ][nf * 8 + t4 * 2 + 1] = p1;
                Ps[rr + g + 8][nf * 8 + t4 * 2    ] = p2;
                Ps[rr + g + 8][nf * 8 + t4 * 2 + 1] = p3;
                sum0 += p0 + p1;
                sum1 += p2 + p3;
            }
            sum0 += __shfl_xor_sync(0xffffffffu, sum0, 1);
            sum0 += __shfl_xor_sync(0xffffffffu, sum0, 2);
            sum1 += __shfl_xor_sync(0xffffffffu, sum1, 1);
            sum1 += __shfl_xor_sync(0xffffffffu, sum1, 2);

            l0 = l0 * sc0 + sum0;  m0 = nm0;
            l1 = l1 * sc1 + sum1;  m1 = nm1;

            #pragma unroll
            for (int dn = 0; dn < 8; dn++) {
                o[dn][0] *= sc0; o[dn][1] *= sc0;
                o[dn][2] *= sc1; o[dn][3] *= sc1;
            }
            __syncwarp();

            // ---- O += P V ----
            #pragma unroll
            for (int kf = 0; kf < 4; kf++) {
                uint32_t pa0 = __float_as_uint(Ps[rr + g    ][kf * 8 + t4]);
                uint32_t pa1 = __float_as_uint(Ps[rr + g + 8][kf * 8 + t4]);
                uint32_t pa2 = __float_as_uint(Ps[rr + g    ][kf * 8 + t4 + 4]);
                uint32_t pa3 = __float_as_uint(Ps[rr + g + 8][kf * 8 + t4 + 4]);
                #pragma unroll
                for (int dn = 0; dn < 8; dn++) {
                    uint32_t b0 = __float_as_uint(Vs[kf * 8 + t4    ][dn * 8 + g]);
                    uint32_t b1 = __float_as_uint(Vs[kf * 8 + t4 + 4][dn * 8 + g]);
                    mma8(o[dn], pa0, pa1, pa2, pa3, b0, b1);
                }
            }
        }

        __syncthreads();
        if (kt + 1 < nkt) {
            #pragma unroll
            for (int j = 0; j < 8; j++) {
                int i = tid + j * 256;
                int r = i >> 6, d = i & 63;
                Ks[r][d] = rk[j];
                Vs[r][d] = rv[j];
            }
        }
        __syncthreads();
    }

    // ---- epilogue: normalize, round, write [B,S,H,D] ----
    const float inv0 = 1.0f / l0;
    const float inv1 = 1.0f / l1;
    const int r0 = q0 + warp * 16 + g;
    float* ob = g_attn + (size_t)b * SEQ * EMBED + (size_t)h * HEAD;
    #pragma unroll
    for (int dn = 0; dn < 8; dn++) {
        int d = dn * 8 + t4 * 2;
        ob[(size_t)(r0    ) * EMBED + d    ] = rnd32(o[dn][0] * inv0);
        ob[(size_t)(r0    ) * EMBED + d + 1] = rnd32(o[dn][1] * inv0);
        ob[(size_t)(r0 + 8) * EMBED + d    ] = rnd32(o[dn][2] * inv1);
        ob[(size_t)(r0 + 8) * EMBED + d + 1] = rnd32(o[dn][3] * inv1);
    }
}

// ============================================================================
// Kernel 3: output projection.  g_attn[8192,1024] @ g_wot[1024,1024] + bo.
// ============================================================================
__global__ __launch_bounds__(256) void proj_kernel(
    const float* __restrict__ bo,
    float* __restrict__ out)
{
    __shared__ float As[2][128][20];
    __shared__ float Bs[2][16][136];

    const int e0 = blockIdx.x * 128;
    const int m0 = blockIdx.y * 128;

    const int tid  = threadIdx.x;
    const int lane = tid & 31;
    const int warp = tid >> 5;
    const int g    = lane >> 2;
    const int t4   = lane & 3;
    const int wm   = warp & 3;
    const int wn   = warp >> 2;

    int arA[2], acA[2], bkB[2], bcB[2];
    const float* agp[2];
    const float* bgp[2];
    #pragma unroll
    for (int j = 0; j < 2; j++) {
        int chunk = tid + j * 256;
        arA[j] = chunk >> 2; acA[j] = (chunk & 3) * 4;
        agp[j] = g_attn + (size_t)(m0 + arA[j]) * EMBED + acA[j];
        bkB[j] = chunk >> 5; bcB[j] = (chunk & 31) * 4;
        bgp[j] = g_wot + (size_t)bkB[j] * EMBED + e0 + bcB[j];
    }

    float c[2][8][4];
    #pragma unroll
    for (int mi = 0; mi < 2; mi++)
        #pragma unroll
        for (int ni = 0; ni < 8; ni++)
            #pragma unroll
            for (int e = 0; e < 4; e++) c[mi][ni][e] = 0.0f;

    #pragma unroll
    for (int j = 0; j < 2; j++) {
        cp16(&As[0][arA[j]][acA[j]], agp[j]);
        cp16(&Bs[0][bkB[j]][bcB[j]], bgp[j]);
    }
    CP_COMMIT();
    CP_WAIT0();
    __syncthreads();

    const int NK = EMBED / 16;
    #pragma unroll 2
    for (int it = 0; it < NK; it++) {
        const int buf = it & 1;
        if (it + 1 < NK) {
            const int f = (it + 1) * 16;
            #pragma unroll
            for (int j = 0; j < 2; j++) {
                cp16(&As[buf ^ 1][arA[j]][acA[j]], agp[j] + f);
                cp16(&Bs[buf ^ 1][bkB[j]][bcB[j]], bgp[j] + (size_t)f * EMBED);
            }
            CP_COMMIT();
        }

        #pragma unroll
        for (int ks = 0; ks < 2; ks++) {
            const int kb = ks * 8;
            uint32_t a[2][4];
            #pragma unroll
            for (int mi = 0; mi < 2; mi++) {
                int r = wm * 32 + mi * 16;
                a[mi][0] = __float_as_uint(As[buf][r + g    ][kb + t4]);
                a[mi][1] = __float_as_uint(As[buf][r + g + 8][kb + t4]);
                a[mi][2] = __float_as_uint(As[buf][r + g    ][kb + t4 + 4]);
                a[mi][3] = __float_as_uint(As[buf][r + g + 8][kb + t4 + 4]);
            }
            #pragma unroll
            for (int ni = 0; ni < 8; ni++) {
                uint32_t b0 = __float_as_uint(Bs[buf][kb + t4    ][wn * 64 + ni * 8 + g]);
                uint32_t b1 = __float_as_uint(Bs[buf][kb + t4 + 4][wn * 64 + ni * 8 + g]);
                #pragma unroll
                for (int mi = 0; mi < 2; mi++)
                    mma8(c[mi][ni], a[mi][0], a[mi][1], a[mi][2], a[mi][3], b0, b1);
            }
        }

        CP_WAIT0();
        __syncthreads();
    }

    #pragma unroll
    for (int mi = 0; mi < 2; mi++) {
        int r0 = m0 + wm * 32 + mi * 16 + g;
        #pragma unroll
        for (int ni = 0; ni < 8; ni++) {
            int e = e0 + wn * 64 + ni * 8 + t4 * 2;
            out[(size_t)(r0    ) * EMBED + e    ] = c[mi][ni][0] + bo[e];
            out[(size_t)(r0    ) * EMBED + e + 1] = c[mi][ni][1] + bo[e + 1];
            out[(size_t)(r0 + 8) * EMBED + e    ] = c[mi][ni][2] + bo[e];
            out[(size_t)(r0 + 8) * EMBED + e + 1] = c[mi][ni][3] + bo[e + 1];
        }
    }
}

// ============================================================================
extern "C" void kernel_launch(void* const* d_in, const int* in_sizes, int n_in,
                              void* d_out, int out_size)
{
    const float* x  = (const float*)d_in[0];
    const float* Wq = (const float*)d_in[1];
    const float* Wk = (const float*)d_in[2];
    const float* Wv = (const float*)d_in[3];
    const float* Wo = (const float*)d_in[4];
    const float* bo = (const float*)d_in[5];
    float* out = (float*)d_out;

    (void)in_sizes; (void)n_in; (void)out_size;

    round_x_kernel<<<NTOK * EMBED / 1024, 256>>>(x);
    pack_w_kernel<<<EMBED * QKVN / 256, 256>>>(Wq, Wk, Wv);
    trans_wo_kernel<<<dim3(EMBED / 32, EMBED / 32), 256>>>(Wo);

    qkv_kernel<<<dim3(QKVN / 128, NTOK / 128), 256>>>();
    attn_kernel<<<dim3(SEQ / 128, BATCH * NHEADS), 256>>>();
    proj_kernel<<<dim3(EMBED / 128, NTOK / 128), 256>>>(bo, out);
}

// round 5
// speedup vs baseline: 1.0046x; 1.0046x over previous
#include <cuda_runtime.h>
#include <stdint.h>
#include <math.h>

#define BATCH  4
#define NHEADS 16
#define HEAD   64
#define SEQ    2048
#define EMBED  1024
#define QKVN   3072
#define NTOK   (BATCH * SEQ)   // 8192

// ---------------- scratch (device globals: allocation-free) ----------------
__device__ float g_q[BATCH * NHEADS * SEQ * HEAD];   // [B,H,S,D], tf32-rounded, Q pre-scaled
__device__ float g_k[BATCH * NHEADS * SEQ * HEAD];
__device__ float g_v[BATCH * NHEADS * SEQ * HEAD];
__device__ float g_attn[BATCH * SEQ * EMBED];        // [B,S,H*D], tf32-rounded
__device__ float g_xr[NTOK * EMBED];                 // X, tf32-rounded
__device__ float g_wqkv[EMBED * QKVN];               // packed [k][n], tf32-rounded
__device__ float g_wot[EMBED * EMBED];               // Wo^T [f][e], tf32-rounded

// ---------------- helpers ----------------
__device__ __forceinline__ float rnd32(float f) {
    uint32_t r;
    asm("cvt.rna.tf32.f32 %0, %1;" : "=r"(r) : "f"(f));
    return __uint_as_float(r);
}

__device__ __forceinline__ void mma8(float* c,
                                     uint32_t a0, uint32_t a1, uint32_t a2, uint32_t a3,
                                     uint32_t b0, uint32_t b1) {
    asm volatile(
        "mma.sync.aligned.m16n8k8.row.col.f32.tf32.tf32.f32 "
        "{%0,%1,%2,%3}, {%4,%5,%6,%7}, {%8,%9}, {%0,%1,%2,%3};"
        : "+f"(c[0]), "+f"(c[1]), "+f"(c[2]), "+f"(c[3])
        : "r"(a0), "r"(a1), "r"(a2), "r"(a3), "r"(b0), "r"(b1));
}

__device__ __forceinline__ void cp16(void* smem, const void* gmem) {
    uint32_t sa = (uint32_t)__cvta_generic_to_shared(smem);
    asm volatile("cp.async.cg.shared.global [%0], [%1], 16;" :: "r"(sa), "l"(gmem));
}
#define CP_COMMIT() asm volatile("cp.async.commit_group;")
#define CP_WAIT1()  asm volatile("cp.async.wait_group 1;")

// smem sizes (bytes)
#define QKV_SMEM  ((3 * 128 * 20 + 3 * 16 * 136) * 4)    // 56832
#define ATTN_SMEM ((3 * 32 * 68 + 3 * 32 * 72 + 128 * 36) * 4)  // 72192

// ============================================================================
// Prep kernels: round/pack operands once so inner loops need no cvt.
// ============================================================================
__global__ __launch_bounds__(256) void round_x_kernel(const float* __restrict__ x) {
    int i = (blockIdx.x * 256 + threadIdx.x) * 4;
    float4 v = *(const float4*)(x + i);
    v.x = rnd32(v.x); v.y = rnd32(v.y); v.z = rnd32(v.z); v.w = rnd32(v.w);
    *(float4*)(g_xr + i) = v;
}

__global__ __launch_bounds__(256) void pack_w_kernel(
    const float* __restrict__ Wq, const float* __restrict__ Wk, const float* __restrict__ Wv) {
    int i = blockIdx.x * 256 + threadIdx.x;      // over EMBED*QKVN
    int n = i % QKVN;
    int k = i / QKVN;
    int mat = n >> 10;
    int hn  = n & 1023;
    int h = hn >> 6, d = hn & 63;
    const float* w = (mat == 0) ? Wq : ((mat == 1) ? Wk : Wv);
    g_wqkv[i] = rnd32(w[((size_t)h * EMBED + k) * HEAD + d]);
}

__global__ __launch_bounds__(256) void trans_wo_kernel(const float* __restrict__ Wo) {
    __shared__ float t[32][33];
    const int e0 = blockIdx.x * 32;
    const int f0 = blockIdx.y * 32;
    const int tx = threadIdx.x & 31;
    const int ty = threadIdx.x >> 5;   // 0..7
    #pragma unroll
    for (int j = 0; j < 4; j++)
        t[ty + j * 8][tx] = Wo[(size_t)(e0 + ty + j * 8) * EMBED + f0 + tx];
    __syncthreads();
    #pragma unroll
    for (int j = 0; j < 4; j++)
        g_wot[(size_t)(f0 + ty + j * 8) * EMBED + e0 + tx] = rnd32(t[tx][ty + j * 8]);
}

// ============================================================================
// Shared GEMM body: C[128x128] = A[128xK] * B[Kx128], A rows strided lda,
// B rows (k-major) strided ldb.  3-stage cp.async ring, wait_group 1,
// one barrier per K16 iteration.
// ============================================================================
struct GemmAcc { float c[2][8][4]; };

__device__ __forceinline__ void gemm128_body(
    GemmAcc& acc,
    const float* __restrict__ aBase,   // A block origin (row m0, col 0)
    const float* __restrict__ bBase,   // B block origin (row 0, col n0)
    int lda, int ldb, int NK)
{
    extern __shared__ float smem[];
    float (*As)[128][20] = (float(*)[128][20])smem;
    float (*Bs)[16][136] = (float(*)[16][136])(smem + 3 * 128 * 20);

    const int tid  = threadIdx.x;
    const int lane = tid & 31;
    const int warp = tid >> 5;
    const int g    = lane >> 2;
    const int t4   = lane & 3;
    const int wm   = warp & 3;
    const int wn   = warp >> 2;

    int arA[2], acA[2], bkB[2], bcB[2];
    const float* agp[2];
    const float* bgp[2];
    #pragma unroll
    for (int j = 0; j < 2; j++) {
        int chunk = tid + j * 256;
        arA[j] = chunk >> 2; acA[j] = (chunk & 3) * 4;
        agp[j] = aBase + (size_t)arA[j] * lda + acA[j];
        bkB[j] = chunk >> 5; bcB[j] = (chunk & 31) * 4;
        bgp[j] = bBase + (size_t)bkB[j] * ldb + bcB[j];
    }

    // prologue: stages 0,1
    #pragma unroll
    for (int st = 0; st < 2; st++) {
        const int kc = st * 16;
        #pragma unroll
        for (int j = 0; j < 2; j++) {
            cp16(&As[st][arA[j]][acA[j]], agp[j] + kc);
            cp16(&Bs[st][bkB[j]][bcB[j]], bgp[j] + (size_t)kc * ldb);
        }
        CP_COMMIT();
    }

    int sc = 0;   // compute stage
    for (int it = 0; it < NK; it++) {
        CP_WAIT1();
        __syncthreads();

        if (it + 2 < NK) {
            int sp = sc + 2; if (sp >= 3) sp -= 3;
            const int kc = (it + 2) * 16;
            #pragma unroll
            for (int j = 0; j < 2; j++) {
                cp16(&As[sp][arA[j]][acA[j]], agp[j] + kc);
                cp16(&Bs[sp][bkB[j]][bcB[j]], bgp[j] + (size_t)kc * ldb);
            }
            CP_COMMIT();
        }

        #pragma unroll
        for (int ks = 0; ks < 2; ks++) {
            const int kb = ks * 8;
            uint32_t a[2][4];
            #pragma unroll
            for (int mi = 0; mi < 2; mi++) {
                int r = wm * 32 + mi * 16;
                a[mi][0] = __float_as_uint(As[sc][r + g    ][kb + t4]);
                a[mi][1] = __float_as_uint(As[sc][r + g + 8][kb + t4]);
                a[mi][2] = __float_as_uint(As[sc][r + g    ][kb + t4 + 4]);
                a[mi][3] = __float_as_uint(As[sc][r + g + 8][kb + t4 + 4]);
            }
            #pragma unroll
            for (int ni = 0; ni < 8; ni++) {
                uint32_t b0 = __float_as_uint(Bs[sc][kb + t4    ][wn * 64 + ni * 8 + g]);
                uint32_t b1 = __float_as_uint(Bs[sc][kb + t4 + 4][wn * 64 + ni * 8 + g]);
                #pragma unroll
                for (int mi = 0; mi < 2; mi++)
                    mma8(acc.c[mi][ni], a[mi][0], a[mi][1], a[mi][2], a[mi][3], b0, b1);
            }
        }

        if (++sc == 3) sc = 0;
    }
}

// ============================================================================
// Kernel 1: QKV GEMM -> scatter to g_q/g_k/g_v [B,H,S,D].
// ============================================================================
__global__ __launch_bounds__(256) void qkv_kernel()
{
    const int n0 = blockIdx.x * 128;
    const int m0 = blockIdx.y * 128;

    GemmAcc acc;
    #pragma unroll
    for (int mi = 0; mi < 2; mi++)
        #pragma unroll
        for (int ni = 0; ni < 8; ni++)
            #pragma unroll
            for (int e = 0; e < 4; e++) acc.c[mi][ni][e] = 0.0f;

    gemm128_body(acc, g_xr + (size_t)m0 * EMBED, g_wqkv + n0, EMBED, QKVN, EMBED / 16);

    const int lane = threadIdx.x & 31;
    const int warp = threadIdx.x >> 5;
    const int g    = lane >> 2;
    const int t4   = lane & 3;
    const int wm   = warp & 3;
    const int wn   = warp >> 2;

    const int mat = n0 >> 10;
    const int b   = m0 >> 11;
    const int s0l = m0 & 2047;
    const int h   = ((n0 & 1023) >> 6) + wn;
    float* dstm = (mat == 0) ? g_q : ((mat == 1) ? g_k : g_v);
    float* dst  = dstm + ((size_t)(b * NHEADS + h) * SEQ) * HEAD;
    const float scale = (mat == 0) ? 0.125f : 1.0f;

    #pragma unroll
    for (int mi = 0; mi < 2; mi++) {
        int s0r = s0l + wm * 32 + mi * 16 + g;
        #pragma unroll
        for (int ni = 0; ni < 8; ni++) {
            int d = ni * 8 + t4 * 2;
            dst[(size_t)(s0r    ) * HEAD + d    ] = rnd32(acc.c[mi][ni][0] * scale);
            dst[(size_t)(s0r    ) * HEAD + d + 1] = rnd32(acc.c[mi][ni][1] * scale);
            dst[(size_t)(s0r + 8) * HEAD + d    ] = rnd32(acc.c[mi][ni][2] * scale);
            dst[(size_t)(s0r + 8) * HEAD + d + 1] = rnd32(acc.c[mi][ni][3] * scale);
        }
    }
}

// ============================================================================
// Kernel 2: causal flash attention.  3-stage cp.async K/V ring.
// BM=128 (8 warps x 16 rows), BN=32, D=64.
// ============================================================================
__global__ __launch_bounds__(256, 1) void attn_kernel()
{
    extern __shared__ float smem[];
    float (*Ks)[32][68] = (float(*)[32][68])smem;
    float (*Vs)[32][72] = (float(*)[32][72])(smem + 3 * 32 * 68);
    float (*Ps)[36]     = (float(*)[36])(smem + 3 * 32 * 68 + 3 * 32 * 72);

    const int bh = blockIdx.y;
    const int b  = bh >> 4;
    const int h  = bh & 15;
    const int qt = blockIdx.x;
    const int q0 = qt * 128;

    const int tid  = threadIdx.x;
    const int lane = tid & 31;
    const int warp = tid >> 5;
    const int g    = lane >> 2;
    const int t4   = lane & 3;

    const float* qp = g_q + ((size_t)bh * SEQ + q0) * HEAD;
    const float* kp = g_k + (size_t)bh * SEQ * HEAD;
    const float* vp = g_v + (size_t)bh * SEQ * HEAD;

    // K/V staging descriptors: 2 chunks of 16B per thread per matrix
    int cr[2], cd[2];
    #pragma unroll
    for (int j = 0; j < 2; j++) {
        int chunk = tid + j * 256;
        cr[j] = chunk >> 4; cd[j] = (chunk & 15) * 4;
    }

    // ---- stage Q through Ps, build A-frags (raw bits; already rounded) ----
    uint32_t qa[8][4];
    #pragma unroll
    for (int round = 0; round < 2; round++) {
        const int c0 = round * 32;
        #pragma unroll
        for (int i = tid; i < 128 * 32; i += 256) {
            int r = i >> 5, cc = i & 31;
            Ps[r][cc] = qp[(size_t)r * HEAD + c0 + cc];
        }
        __syncthreads();
        #pragma unroll
        for (int kf = 0; kf < 4; kf++) {
            int kfi = round * 4 + kf;
            int rr = warp * 16;
            qa[kfi][0] = __float_as_uint(Ps[rr + g    ][kf * 8 + t4]);
            qa[kfi][1] = __float_as_uint(Ps[rr + g + 8][kf * 8 + t4]);
            qa[kfi][2] = __float_as_uint(Ps[rr + g    ][kf * 8 + t4 + 4]);
            qa[kfi][3] = __float_as_uint(Ps[rr + g + 8][kf * 8 + t4 + 4]);
        }
        __syncthreads();
    }

    float o[8][4];
    #pragma unroll
    for (int dn = 0; dn < 8; dn++)
        #pragma unroll
        for (int e = 0; e < 4; e++) o[dn][e] = 0.0f;

    float m0 = -1e30f, m1 = -1e30f, l0 = 0.0f, l1 = 0.0f;

    const int nkt   = (qt + 1) * 4;     // >= 4
    const int row0b = q0 + warp * 16;
    const int qmaxw = row0b + 15;

    // prologue: tiles 0,1
    #pragma unroll
    for (int st = 0; st < 2; st++) {
        const size_t base = (size_t)st * 32 * HEAD;
        #pragma unroll
        for (int j = 0; j < 2; j++) {
            cp16(&Ks[st][cr[j]][cd[j]], kp + base + (size_t)cr[j] * HEAD + cd[j]);
            cp16(&Vs[st][cr[j]][cd[j]], vp + base + (size_t)cr[j] * HEAD + cd[j]);
        }
        CP_COMMIT();
    }

    int sc = 0;
    for (int kt = 0; kt < nkt; kt++) {
        const int k0 = kt * 32;

        CP_WAIT1();
        __syncthreads();

        if (kt + 2 < nkt) {
            int sp = sc + 2; if (sp >= 3) sp -= 3;
            const size_t base = (size_t)(k0 + 64) * HEAD;
            #pragma unroll
            for (int j = 0; j < 2; j++) {
                cp16(&Ks[sp][cr[j]][cd[j]], kp + base + (size_t)cr[j] * HEAD + cd[j]);
                cp16(&Vs[sp][cr[j]][cd[j]], vp + base + (size_t)cr[j] * HEAD + cd[j]);
            }
            CP_COMMIT();
        }

        if (k0 <= qmaxw) {
            // ---- S = Q K^T ----
            float s[4][4];
            #pragma unroll
            for (int nf = 0; nf < 4; nf++)
                #pragma unroll
                for (int e = 0; e < 4; e++) s[nf][e] = 0.0f;

            #pragma unroll
            for (int kf = 0; kf < 8; kf++) {
                #pragma unroll
                for (int nf = 0; nf < 4; nf++) {
                    uint32_t b0 = __float_as_uint(Ks[sc][nf * 8 + g][kf * 8 + t4]);
                    uint32_t b1 = __float_as_uint(Ks[sc][nf * 8 + g][kf * 8 + t4 + 4]);
                    mma8(s[nf], qa[kf][0], qa[kf][1], qa[kf][2], qa[kf][3], b0, b1);
                }
            }

            // ---- causal mask ----
            const int r0 = row0b + g;
            const int r1 = r0 + 8;
            #pragma unroll
            for (int nf = 0; nf < 4; nf++) {
                int col0 = k0 + nf * 8 + t4 * 2;
                if (col0     > r0) s[nf][0] = -1e30f;
                if (col0 + 1 > r0) s[nf][1] = -1e30f;
                if (col0     > r1) s[nf][2] = -1e30f;
                if (col0 + 1 > r1) s[nf][3] = -1e30f;
            }

            // ---- online softmax ----
            float rm0 = -1e30f, rm1 = -1e30f;
            #pragma unroll
            for (int nf = 0; nf < 4; nf++) {
                rm0 = fmaxf(rm0, fmaxf(s[nf][0], s[nf][1]));
                rm1 = fmaxf(rm1, fmaxf(s[nf][2], s[nf][3]));
            }
            rm0 = fmaxf(rm0, __shfl_xor_sync(0xffffffffu, rm0, 1));
            rm0 = fmaxf(rm0, __shfl_xor_sync(0xffffffffu, rm0, 2));
            rm1 = fmaxf(rm1, __shfl_xor_sync(0xffffffffu, rm1, 1));
            rm1 = fmaxf(rm1, __shfl_xor_sync(0xffffffffu, rm1, 2));

            float nm0 = fmaxf(m0, rm0), nm1 = fmaxf(m1, rm1);
            float sc0 = __expf(m0 - nm0), sc1 = __expf(m1 - nm1);

            float sum0 = 0.0f, sum1 = 0.0f;
            const int rr = warp * 16;
            #pragma unroll
            for (int nf = 0; nf < 4; nf++) {
                float p0 = rnd32(__expf(s[nf][0] - nm0));
                float p1 = rnd32(__expf(s[nf][1] - nm0));
                float p2 = rnd32(__expf(s[nf][2] - nm1));
                float p3 = rnd32(__expf(s[nf][3] - nm1));
                Ps[rr + g    ][nf * 8 + t4 * 2    ] = p0;
                Ps[rr + g    ][nf * 8 + t4 * 2 + 1] = p1;
                Ps[rr + g + 8][nf * 8 + t4 * 2    ] = p2;
                Ps[rr + g + 8][nf * 8 + t4 * 2 + 1] = p3;
                sum0 += p0 + p1;
                sum1 += p2 + p3;
            }
            sum0 += __shfl_xor_sync(0xffffffffu, sum0, 1);
            sum0 += __shfl_xor_sync(0xffffffffu, sum0, 2);
            sum1 += __shfl_xor_sync(0xffffffffu, sum1, 1);
            sum1 += __shfl_xor_sync(0xffffffffu, sum1, 2);

            l0 = l0 * sc0 + sum0;  m0 = nm0;
            l1 = l1 * sc1 + sum1;  m1 = nm1;

            #pragma unroll
            for (int dn = 0; dn < 8; dn++) {
                o[dn][0] *= sc0; o[dn][1] *= sc0;
                o[dn][2] *= sc1; o[dn][3] *= sc1;
            }
            __syncwarp();

            // ---- O += P V ----
            #pragma unroll
            for (int kf = 0; kf < 4; kf++) {
                uint32_t pa0 = __float_as_uint(Ps[rr + g    ][kf * 8 + t4]);
                uint32_t pa1 = __float_as_uint(Ps[rr + g + 8][kf * 8 + t4]);
                uint32_t pa2 = __float_as_uint(Ps[rr + g    ][kf * 8 + t4 + 4]);
                uint32_t pa3 = __float_as_uint(Ps[rr + g + 8][kf * 8 + t4 + 4]);
                #pragma unroll
                for (int dn = 0; dn < 8; dn++) {
                    uint32_t b0 = __float_as_uint(Vs[sc][kf * 8 + t4    ][dn * 8 + g]);
                    uint32_t b1 = __float_as_uint(Vs[sc][kf * 8 + t4 + 4][dn * 8 + g]);
                    mma8(o[dn], pa0, pa1, pa2, pa3, b0, b1);
                }
            }
            __syncwarp();
        }

        if (++sc == 3) sc = 0;
    }

    // ---- epilogue: normalize, round, write [B,S,H,D] ----
    const float inv0 = 1.0f / l0;
    const float inv1 = 1.0f / l1;
    const int r0 = q0 + warp * 16 + g;
    float* ob = g_attn + (size_t)b * SEQ * EMBED + (size_t)h * HEAD;
    #pragma unroll
    for (int dn = 0; dn < 8; dn++) {
        int d = dn * 8 + t4 * 2;
        ob[(size_t)(r0    ) * EMBED + d    ] = rnd32(o[dn][0] * inv0);
        ob[(size_t)(r0    ) * EMBED + d + 1] = rnd32(o[dn][1] * inv0);
        ob[(size_t)(r0 + 8) * EMBED + d    ] = rnd32(o[dn][2] * inv1);
        ob[(size_t)(r0 + 8) * EMBED + d + 1] = rnd32(o[dn][3] * inv1);
    }
}

// ============================================================================
// Kernel 3: output projection.  g_attn[8192,1024] @ g_wot[1024,1024] + bo.
// ============================================================================
__global__ __launch_bounds__(256) void proj_kernel(
    const float* __restrict__ bo,
    float* __restrict__ out)
{
    const int e0 = blockIdx.x * 128;
    const int m0 = blockIdx.y * 128;

    GemmAcc acc;
    #pragma unroll
    for (int mi = 0; mi < 2; mi++)
        #pragma unroll
        for (int ni = 0; ni < 8; ni++)
            #pragma unroll
            for (int e = 0; e < 4; e++) acc.c[mi][ni][e] = 0.0f;

    gemm128_body(acc, g_attn + (size_t)m0 * EMBED, g_wot + e0, EMBED, EMBED, EMBED / 16);

    const int lane = threadIdx.x & 31;
    const int warp = threadIdx.x >> 5;
    const int g    = lane >> 2;
    const int t4   = lane & 3;
    const int wm   = warp & 3;
    const int wn   = warp >> 2;

    #pragma unroll
    for (int mi = 0; mi < 2; mi++) {
        int r0 = m0 + wm * 32 + mi * 16 + g;
        #pragma unroll
        for (int ni = 0; ni < 8; ni++) {
            int e = e0 + wn * 64 + ni * 8 + t4 * 2;
            out[(size_t)(r0    ) * EMBED + e    ] = acc.c[mi][ni][0] + bo[e];
            out[(size_t)(r0    ) * EMBED + e + 1] = acc.c[mi][ni][1] + bo[e + 1];
            out[(size_t)(r0 + 8) * EMBED + e    ] = acc.c[mi][ni][2] + bo[e];
            out[(size_t)(r0 + 8) * EMBED + e + 1] = acc.c[mi][ni][3] + bo[e + 1];
        }
    }
}

// ============================================================================
extern "C" void kernel_launch(void* const* d_in, const int* in_sizes, int n_in,
                              void* d_out, int out_size)
{
    const float* x  = (const float*)d_in[0];
    const float* Wq = (const float*)d_in[1];
    const float* Wk = (const float*)d_in[2];
    const float* Wv = (const float*)d_in[3];
    const float* Wo = (const float*)d_in[4];
    const float* bo = (const float*)d_in[5];
    float* out = (float*)d_out;

    (void)in_sizes; (void)n_in; (void)out_size;

    // opt-in to >48KB dynamic smem (host-side attribute set; not a stream op)
    cudaFuncSetAttribute(qkv_kernel,  cudaFuncAttributeMaxDynamicSharedMemorySize, QKV_SMEM);
    cudaFuncSetAttribute(attn_kernel, cudaFuncAttributeMaxDynamicSharedMemorySize, ATTN_SMEM);
    cudaFuncSetAttribute(proj_kernel, cudaFuncAttributeMaxDynamicSharedMemorySize, QKV_SMEM);

    round_x_kernel<<<NTOK * EMBED / 1024, 256>>>(x);
    pack_w_kernel<<<EMBED * QKVN / 256, 256>>>(Wq, Wk, Wv);
    trans_wo_kernel<<<dim3(EMBED / 32, EMBED / 32), 256>>>(Wo);

    qkv_kernel<<<dim3(QKVN / 128, NTOK / 128), 256, QKV_SMEM>>>();
    attn_kernel<<<dim3(SEQ / 128, BATCH * NHEADS), 256, ATTN_SMEM>>>();
    proj_kernel<<<dim3(EMBED / 128, NTOK / 128), 256, QKV_SMEM>>>(bo, out);
}